// round 2
// baseline (speedup 1.0000x reference)
#include <cuda_runtime.h>
#include <cuda_bf16.h>
#include <cstdint>

// ============================================================================
// Problem constants
// ============================================================================
#define N_ROWS   65536
#define IN_DIM   256
#define OUT_DIM  256
#define NTYPES   8
#define BM       64                        // rows per GEMM tile
#define MAXTILES (N_ROWS / BM + NTYPES)    // 1032
#define KC       64                        // K-chunk (64 fp32 -> 128B bf16 rows)
#define NCHUNK   (IN_DIM / KC)             // 4
#define GTHREADS 256

// SMEM layout (bytes):
//  [0]      s_idx[64]            (256B)
//  [256]    s_bias[256]          (1KB)
//  [2048]   Ahi  64x64 bf16      (8KB)
//  [10240]  Alo                  (8KB)
//  [18432]  Bhi 256x64 bf16      (32KB)
//  [51200]  Blo                  (32KB)
#define SMEM_BYTES 83968

// ============================================================================
// Device scratch
// ============================================================================
__device__ int g_counts[NTYPES];
__device__ int g_cursor[NTYPES];
__device__ int g_padstart[NTYPES];
__device__ int g_idx[MAXTILES * BM];
__device__ int g_tiletype[MAXTILES];

// ============================================================================
// Helpers
// ============================================================================
__device__ __forceinline__ uint32_t smem_u32(const void* p) {
    uint32_t a;
    asm("{ .reg .u64 t; cvta.to.shared.u64 t, %1; cvt.u32.u64 %0, t; }" : "=r"(a) : "l"(p));
    return a;
}

__device__ __forceinline__ uint32_t swz(uint32_t off) { return off ^ ((off >> 3) & 0x70); }

__device__ __forceinline__ void ldsm4(uint32_t& r0, uint32_t& r1, uint32_t& r2, uint32_t& r3,
                                      uint32_t addr) {
    asm volatile("ldmatrix.sync.aligned.m8n8.x4.shared.b16 {%0,%1,%2,%3}, [%4];"
                 : "=r"(r0), "=r"(r1), "=r"(r2), "=r"(r3) : "r"(addr));
}

__device__ __forceinline__ void mma16816(float* c, const uint32_t* a, uint32_t b0, uint32_t b1) {
    asm volatile("mma.sync.aligned.m16n8k16.row.col.f32.bf16.bf16.f32 "
                 "{%0,%1,%2,%3}, {%4,%5,%6,%7}, {%8,%9}, {%0,%1,%2,%3};"
                 : "+f"(c[0]), "+f"(c[1]), "+f"(c[2]), "+f"(c[3])
                 : "r"(a[0]), "r"(a[1]), "r"(a[2]), "r"(a[3]), "r"(b0), "r"(b1));
}

// fp32 -> (hi, lo) bf16 split; 4 lanes packed as 2x bf16x2
__device__ __forceinline__ void split4(const float4& v, uint2& h, uint2& l) {
    __nv_bfloat16 h0 = __float2bfloat16_rn(v.x);
    __nv_bfloat16 h1 = __float2bfloat16_rn(v.y);
    __nv_bfloat16 h2 = __float2bfloat16_rn(v.z);
    __nv_bfloat16 h3 = __float2bfloat16_rn(v.w);
    __nv_bfloat16 l0 = __float2bfloat16_rn(v.x - __bfloat162float(h0));
    __nv_bfloat16 l1 = __float2bfloat16_rn(v.y - __bfloat162float(h1));
    __nv_bfloat16 l2 = __float2bfloat16_rn(v.z - __bfloat162float(h2));
    __nv_bfloat16 l3 = __float2bfloat16_rn(v.w - __bfloat162float(h3));
    h.x = (uint32_t)__bfloat16_as_ushort(h0) | ((uint32_t)__bfloat16_as_ushort(h1) << 16);
    h.y = (uint32_t)__bfloat16_as_ushort(h2) | ((uint32_t)__bfloat16_as_ushort(h3) << 16);
    l.x = (uint32_t)__bfloat16_as_ushort(l0) | ((uint32_t)__bfloat16_as_ushort(l1) << 16);
    l.y = (uint32_t)__bfloat16_as_ushort(l2) | ((uint32_t)__bfloat16_as_ushort(l3) << 16);
}

// ============================================================================
// Binning kernels (counting sort of rows by type, padded per-type to BM)
// ============================================================================
__global__ void k_zero() {
    int tid = threadIdx.x;
    if (tid < NTYPES) { g_counts[tid] = 0; g_cursor[tid] = 0; }
}

__global__ void k_hist(const int* __restrict__ types) {
    __shared__ int c[NTYPES];
    int tid = threadIdx.x;
    if (tid < NTYPES) c[tid] = 0;
    __syncthreads();
    int i = blockIdx.x * blockDim.x + tid;
    atomicAdd(&c[types[i]], 1);
    __syncthreads();
    if (tid < NTYPES) atomicAdd(&g_counts[tid], c[tid]);
}

__global__ void k_scan() {
    __shared__ int s_start[NTYPES], s_tiles[NTYPES];
    int tid = threadIdx.x;
    if (tid == 0) {
        int off = 0;
        for (int t = 0; t < NTYPES; t++) {
            s_start[t] = off;
            g_padstart[t] = off;
            int tt = (g_counts[t] + BM - 1) / BM;
            s_tiles[t] = tt;
            off += tt * BM;
        }
    }
    __syncthreads();
    for (int tile = tid; tile < MAXTILES; tile += blockDim.x) {
        int ty = -1;
        int rb = tile * BM;
        for (int t = 0; t < NTYPES; t++)
            if (rb >= s_start[t] && rb < s_start[t] + s_tiles[t] * BM) ty = t;
        g_tiletype[tile] = ty;
    }
    // mark padded slots (at most BM-1 per type) with -1
    for (int j = tid; j < NTYPES * BM; j += blockDim.x) {
        int t = j / BM, o = j % BM;
        int slot = g_counts[t] + o;
        if (slot < s_tiles[t] * BM) g_idx[s_start[t] + slot] = -1;
    }
}

__global__ void k_scatter(const int* __restrict__ types) {
    __shared__ int c[NTYPES], base[NTYPES];
    int tid = threadIdx.x;
    if (tid < NTYPES) c[tid] = 0;
    __syncthreads();
    int i = blockIdx.x * blockDim.x + tid;
    int t = types[i];
    int pos = atomicAdd(&c[t], 1);
    __syncthreads();
    if (tid < NTYPES) base[tid] = atomicAdd(&g_cursor[tid], c[tid]);
    __syncthreads();
    g_idx[g_padstart[t] + base[t] + pos] = i;
}

// ============================================================================
// Grouped GEMM tile kernel: D[64,256] = gather(x)[64,256] * W[t]^T + b[t]
// bf16 3-term split via ldmatrix + mma.sync.m16n8k16 (base sm_103 ISA).
// 8 warps: warp w -> rows [16*(w>>1), +16), cols [128*(w&1), +128).
// ============================================================================
__global__ void __launch_bounds__(GTHREADS, 2)
typed_linear_gemm(const float* __restrict__ x, const float* __restrict__ W,
                  const float* __restrict__ b, float* __restrict__ out) {
    extern __shared__ char smem[];
    const int tile = blockIdx.x;
    const int t = g_tiletype[tile];
    if (t < 0) return;

    const int tid  = threadIdx.x;
    const int wid  = tid >> 5;
    const int lane = tid & 31;
    const uint32_t sb = smem_u32(smem);

    int*   s_idx  = (int*)smem;
    float* s_bias = (float*)(smem + 256);

    if (tid < BM) s_idx[tid] = g_idx[tile * BM + tid];
    s_bias[tid] = b[t * OUT_DIM + tid];
    __syncthreads();

    const int mgrp  = wid >> 1;
    const int nhalf = wid & 1;
    const int j   = lane & 7;
    const int sub = lane >> 3;

    // ldmatrix lane address components (SW128 swizzle, 128B rows)
    const int a_row = mgrp * 16 + j + (sub & 1) * 8;
    const uint32_t a_xr   = (uint32_t)((a_row & 7) * 16);
    const uint32_t a_base = (uint32_t)(a_row * 128) + (uint32_t)((sub >> 1) * 16);

    const int b_row = nhalf * 128 + ((sub >> 1) ? 8 : 0) + j;
    const uint32_t b_xr   = (uint32_t)((b_row & 7) * 16);
    const uint32_t b_base = (uint32_t)(b_row * 128) + (uint32_t)((sub & 1) * 16);

    const uint32_t Ahi_b = sb + 2048;
    const uint32_t Alo_b = sb + 10240;
    const uint32_t Bhi_b = sb + 18432;
    const uint32_t Blo_b = sb + 51200;

    float acc[16][4];
    #pragma unroll
    for (int i = 0; i < 16; ++i)
        #pragma unroll
        for (int q = 0; q < 4; ++q) acc[i][q] = 0.f;

    const float* Wt = W + (size_t)t * OUT_DIM * IN_DIM;

    for (int c = 0; c < NCHUNK; ++c) {
        if (c) __syncthreads();   // previous compute done -> safe to overwrite smem
        const int kb = c * KC;

        // ---- A tile: 64 rows x 64 k gathered, fp32 -> bf16 hi/lo ----
        #pragma unroll
        for (int r = 0; r < 4; ++r) {
            int i4 = r * GTHREADS + tid;          // float4 index, [0,1024)
            int m = i4 >> 4, k4 = i4 & 15;
            int g = s_idx[m];
            float4 v = make_float4(0.f, 0.f, 0.f, 0.f);
            if (g >= 0) v = *(const float4*)(x + (size_t)g * IN_DIM + kb + k4 * 4);
            uint2 h, l;
            split4(v, h, l);
            uint32_t off = swz((uint32_t)(m * 128 + k4 * 8));
            *(uint2*)(smem + 2048 + off)  = h;
            *(uint2*)(smem + 10240 + off) = l;
        }
        // ---- B tile: 256 out-rows x 64 k of W[t] ----
        #pragma unroll
        for (int r = 0; r < 16; ++r) {
            int i4 = r * GTHREADS + tid;          // [0,4096)
            int n = i4 >> 4, k4 = i4 & 15;
            float4 v = *(const float4*)(Wt + (size_t)n * IN_DIM + kb + k4 * 4);
            uint2 h, l;
            split4(v, h, l);
            uint32_t off = swz((uint32_t)(n * 128 + k4 * 8));
            *(uint2*)(smem + 18432 + off) = h;
            *(uint2*)(smem + 51200 + off) = l;
        }
        __syncthreads();

        // ---- compute: 4 K16 steps, 3-term bf16 split ----
        #pragma unroll
        for (int ks = 0; ks < 4; ++ks) {
            const uint32_t kbyte = (uint32_t)(ks * 32);
            uint32_t ah[4], al[4];
            uint32_t aoff = (a_base + kbyte) ^ a_xr;
            ldsm4(ah[0], ah[1], ah[2], ah[3], Ahi_b + aoff);
            ldsm4(al[0], al[1], al[2], al[3], Alo_b + aoff);
            #pragma unroll
            for (int p = 0; p < 8; ++p) {
                uint32_t boff = (b_base + (uint32_t)(p * 2048) + kbyte) ^ b_xr;
                uint32_t bh0, bh1, bh2, bh3, bl0, bl1, bl2, bl3;
                ldsm4(bh0, bh1, bh2, bh3, Bhi_b + boff);
                ldsm4(bl0, bl1, bl2, bl3, Blo_b + boff);
                mma16816(acc[2 * p],     ah, bh0, bh1);
                mma16816(acc[2 * p + 1], ah, bh2, bh3);
                mma16816(acc[2 * p],     ah, bl0, bl1);
                mma16816(acc[2 * p + 1], ah, bl2, bl3);
                mma16816(acc[2 * p],     al, bh0, bh1);
                mma16816(acc[2 * p + 1], al, bh2, bh3);
            }
        }
    }

    // ---- epilogue: bias + scatter-store ----
    const int r0 = mgrp * 16 + (lane >> 2);
    const int g0 = s_idx[r0];
    const int g1 = s_idx[r0 + 8];
    const int colbase = nhalf * 128 + (lane & 3) * 2;
    #pragma unroll
    for (int nt = 0; nt < 16; ++nt) {
        const int col = colbase + nt * 8;
        const float bv0 = s_bias[col], bv1 = s_bias[col + 1];
        if (g0 >= 0) {
            float2 v0 = make_float2(acc[nt][0] + bv0, acc[nt][1] + bv1);
            *(float2*)(out + (size_t)g0 * OUT_DIM + col) = v0;
        }
        if (g1 >= 0) {
            float2 v1 = make_float2(acc[nt][2] + bv0, acc[nt][3] + bv1);
            *(float2*)(out + (size_t)g1 * OUT_DIM + col) = v1;
        }
    }
}

// ============================================================================
// Launch
// ============================================================================
extern "C" void kernel_launch(void* const* d_in, const int* in_sizes, int n_in,
                              void* d_out, int out_size) {
    const float* x     = (const float*)d_in[0];
    const int*   types = (const int*)d_in[1];
    const float* W     = (const float*)d_in[2];
    const float* b     = (const float*)d_in[3];
    float*       out   = (float*)d_out;

    cudaFuncSetAttribute(typed_linear_gemm, cudaFuncAttributeMaxDynamicSharedMemorySize,
                         SMEM_BYTES);

    k_zero<<<1, 32>>>();
    k_hist<<<N_ROWS / 1024, 1024>>>(types);
    k_scan<<<1, 256>>>();
    k_scatter<<<N_ROWS / 1024, 1024>>>(types);
    typed_linear_gemm<<<MAXTILES, GTHREADS, SMEM_BYTES>>>(x, W, b, out);
}

// round 3
// speedup vs baseline: 1.2821x; 1.2821x over previous
#include <cuda_runtime.h>
#include <cuda_bf16.h>
#include <cstdint>

// ============================================================================
// Problem constants
// ============================================================================
#define N_ROWS   65536
#define IN_DIM   256
#define OUT_DIM  256
#define NTYPES   8
#define BM       128                       // rows per GEMM tile
#define MAXTILES (N_ROWS / BM + NTYPES)    // 520
#define KC       64                        // K-chunk
#define NCHUNK   (IN_DIM / KC)             // 4
#define GTHREADS 256

// SMEM layout (bytes):
//  [0]      s_idx[128]                  512B
//  [512]    s_bias[256]                 1KB
//  [2048]   A_raw fp32 staging 128x256B 32KB
//  [34816]  stage0: Ahi 16K|Alo 16K|Bhi 32K|Blo 32K = 96KB
//  [133120] stage1: 96KB
#define OFF_ARAW   2048
#define OFF_STAGE0 34816
#define STAGE_BYTES 98304
#define SMEM_BYTES  231424

// ============================================================================
// Device scratch
// ============================================================================
__device__ int g_counts[NTYPES];
__device__ int g_cursor[NTYPES];
__device__ int g_padstart[NTYPES];
__device__ int g_idx[MAXTILES * BM];
__device__ int g_tiletype[MAXTILES];
__device__ __align__(16) __nv_bfloat16 g_Whi[NTYPES * OUT_DIM * IN_DIM];
__device__ __align__(16) __nv_bfloat16 g_Wlo[NTYPES * OUT_DIM * IN_DIM];

// ============================================================================
// Helpers
// ============================================================================
__device__ __forceinline__ uint32_t smem_u32(const void* p) {
    uint32_t a;
    asm("{ .reg .u64 t; cvta.to.shared.u64 t, %1; cvt.u32.u64 %0, t; }" : "=r"(a) : "l"(p));
    return a;
}

__device__ __forceinline__ uint32_t swz(uint32_t off) { return off ^ ((off >> 3) & 0x70); }

__device__ __forceinline__ void cpa16(uint32_t dst, const void* src) {
    asm volatile("cp.async.cg.shared.global [%0], [%1], 16;" :: "r"(dst), "l"(src));
}
__device__ __forceinline__ void cpa_commit() {
    asm volatile("cp.async.commit_group;");
}
__device__ __forceinline__ void cpa_wait0() {
    asm volatile("cp.async.wait_group 0;" ::: "memory");
}

__device__ __forceinline__ void ldsm4(uint32_t& r0, uint32_t& r1, uint32_t& r2, uint32_t& r3,
                                      uint32_t addr) {
    asm volatile("ldmatrix.sync.aligned.m8n8.x4.shared.b16 {%0,%1,%2,%3}, [%4];"
                 : "=r"(r0), "=r"(r1), "=r"(r2), "=r"(r3) : "r"(addr));
}

__device__ __forceinline__ void mma16816(float* c, const uint32_t* a, uint32_t b0, uint32_t b1) {
    asm volatile("mma.sync.aligned.m16n8k16.row.col.f32.bf16.bf16.f32 "
                 "{%0,%1,%2,%3}, {%4,%5,%6,%7}, {%8,%9}, {%0,%1,%2,%3};"
                 : "+f"(c[0]), "+f"(c[1]), "+f"(c[2]), "+f"(c[3])
                 : "r"(a[0]), "r"(a[1]), "r"(a[2]), "r"(a[3]), "r"(b0), "r"(b1));
}

// fp32 -> (hi, lo) bf16 split; 4 lanes packed as 2x bf16x2
__device__ __forceinline__ void split4(const float4& v, uint2& h, uint2& l) {
    __nv_bfloat16 h0 = __float2bfloat16_rn(v.x);
    __nv_bfloat16 h1 = __float2bfloat16_rn(v.y);
    __nv_bfloat16 h2 = __float2bfloat16_rn(v.z);
    __nv_bfloat16 h3 = __float2bfloat16_rn(v.w);
    __nv_bfloat16 l0 = __float2bfloat16_rn(v.x - __bfloat162float(h0));
    __nv_bfloat16 l1 = __float2bfloat16_rn(v.y - __bfloat162float(h1));
    __nv_bfloat16 l2 = __float2bfloat16_rn(v.z - __bfloat162float(h2));
    __nv_bfloat16 l3 = __float2bfloat16_rn(v.w - __bfloat162float(h3));
    h.x = (uint32_t)__bfloat16_as_ushort(h0) | ((uint32_t)__bfloat16_as_ushort(h1) << 16);
    h.y = (uint32_t)__bfloat16_as_ushort(h2) | ((uint32_t)__bfloat16_as_ushort(h3) << 16);
    l.x = (uint32_t)__bfloat16_as_ushort(l0) | ((uint32_t)__bfloat16_as_ushort(l1) << 16);
    l.y = (uint32_t)__bfloat16_as_ushort(l2) | ((uint32_t)__bfloat16_as_ushort(l3) << 16);
}

// ============================================================================
// W pre-split: fp32 W -> bf16 hi/lo global buffers (run once per launch)
// ============================================================================
__global__ void k_wsplit(const float* __restrict__ W) {
    int i4 = blockIdx.x * blockDim.x + threadIdx.x;   // float4 index, 131072 total
    float4 v = *(const float4*)(W + (size_t)i4 * 4);
    uint2 h, l;
    split4(v, h, l);
    *(uint2*)(g_Whi + (size_t)i4 * 4) = h;
    *(uint2*)(g_Wlo + (size_t)i4 * 4) = l;
}

// ============================================================================
// Binning (counting sort of rows by type, padded per-type to BM)
// ============================================================================
__global__ void k_zero() {
    int tid = threadIdx.x;
    if (tid < NTYPES) { g_counts[tid] = 0; g_cursor[tid] = 0; }
}

__global__ void k_hist(const int* __restrict__ types) {
    __shared__ int c[NTYPES];
    int tid = threadIdx.x;
    if (tid < NTYPES) c[tid] = 0;
    __syncthreads();
    int i = blockIdx.x * blockDim.x + tid;
    int4 tv = *(const int4*)(types + i * 4);
    atomicAdd(&c[tv.x], 1);
    atomicAdd(&c[tv.y], 1);
    atomicAdd(&c[tv.z], 1);
    atomicAdd(&c[tv.w], 1);
    __syncthreads();
    if (tid < NTYPES) atomicAdd(&g_counts[tid], c[tid]);
}

__global__ void k_scan() {
    __shared__ int s_start[NTYPES], s_tiles[NTYPES];
    int tid = threadIdx.x;
    if (tid == 0) {
        int off = 0;
        for (int t = 0; t < NTYPES; t++) {
            s_start[t] = off;
            g_padstart[t] = off;
            int tt = (g_counts[t] + BM - 1) / BM;
            s_tiles[t] = tt;
            off += tt * BM;
        }
    }
    __syncthreads();
    for (int tile = tid; tile < MAXTILES; tile += blockDim.x) {
        int ty = -1;
        int rb = tile * BM;
        for (int t = 0; t < NTYPES; t++)
            if (rb >= s_start[t] && rb < s_start[t] + s_tiles[t] * BM) ty = t;
        g_tiletype[tile] = ty;
    }
    for (int j = tid; j < NTYPES * BM; j += blockDim.x) {
        int t = j / BM, o = j % BM;
        int slot = g_counts[t] + o;
        if (slot < s_tiles[t] * BM) g_idx[s_start[t] + slot] = -1;
    }
}

__global__ void k_scatter(const int* __restrict__ types) {
    __shared__ int c[NTYPES], base[NTYPES];
    int tid = threadIdx.x;
    if (tid < NTYPES) c[tid] = 0;
    __syncthreads();
    int i = blockIdx.x * blockDim.x + tid;
    int4 tv = *(const int4*)(types + i * 4);
    int p0 = atomicAdd(&c[tv.x], 1);
    int p1 = atomicAdd(&c[tv.y], 1);
    int p2 = atomicAdd(&c[tv.z], 1);
    int p3 = atomicAdd(&c[tv.w], 1);
    __syncthreads();
    if (tid < NTYPES) base[tid] = atomicAdd(&g_cursor[tid], c[tid]);
    __syncthreads();
    g_idx[g_padstart[tv.x] + base[tv.x] + p0] = i * 4;
    g_idx[g_padstart[tv.y] + base[tv.y] + p1] = i * 4 + 1;
    g_idx[g_padstart[tv.z] + base[tv.z] + p2] = i * 4 + 2;
    g_idx[g_padstart[tv.w] + base[tv.w] + p3] = i * 4 + 3;
}

// ============================================================================
// Grouped GEMM: per tile, D[128,256] = gather(x) * W[t]^T + b[t]
// bf16 3-term split (xh*wh + xh*wl + xl*wh), ldmatrix + mma.sync.m16n8k16.
// 8 warps: mgrp = wid>>1 -> rows [32*mgrp, +32); nhalf = wid&1 -> cols [128*nhalf, +128).
// cp.async double-buffered stages; A fp32 staged then split in-SMEM.
// ============================================================================
__global__ void __launch_bounds__(GTHREADS, 1)
typed_linear_gemm(const float* __restrict__ x, const float* __restrict__ b,
                  float* __restrict__ out) {
    extern __shared__ char smem[];
    const int tile = blockIdx.x;
    const int t = g_tiletype[tile];
    if (t < 0) return;

    const int tid  = threadIdx.x;
    const int wid  = tid >> 5;
    const int lane = tid & 31;
    const uint32_t sb = smem_u32(smem);

    int*   s_idx  = (int*)smem;
    float* s_bias = (float*)(smem + 512);

    if (tid < BM) s_idx[tid] = g_idx[tile * BM + tid];
    s_bias[tid] = b[t * OUT_DIM + tid];
    __syncthreads();

    const __nv_bfloat16* Whi_t = g_Whi + (size_t)t * OUT_DIM * IN_DIM;
    const __nv_bfloat16* Wlo_t = g_Wlo + (size_t)t * OUT_DIM * IN_DIM;

    // -------- cp.async issue helpers (per chunk) --------
    // A raw: 128 rows x 64 fp32 (256B/row) -> 2048 x 16B; 8 per thread
    // B hi / lo: 256 rows x 64 bf16 (128B/row) -> 2048 x 16B each; 8+8 per thread
    auto issue_chunk = [&](int c) {
        const int kb = c * KC;
        const uint32_t bufB = sb + OFF_STAGE0 + (uint32_t)(c & 1) * STAGE_BYTES + 32768u;
        #pragma unroll
        for (int r = 0; r < 8; ++r) {
            int i16 = r * GTHREADS + tid;          // [0,2048)
            int m = i16 >> 4, k16 = i16 & 15;
            int g = s_idx[m];
            const float* src = x + (size_t)(g < 0 ? 0 : g) * IN_DIM + kb + k16 * 4;
            cpa16(sb + OFF_ARAW + (uint32_t)(i16 * 16), src);
        }
        #pragma unroll
        for (int r = 0; r < 8; ++r) {
            int i16 = r * GTHREADS + tid;          // [0,2048)
            int n = i16 >> 3, k16 = i16 & 7;
            uint32_t dst = swz((uint32_t)(n * 128 + k16 * 16));
            size_t so = (size_t)n * IN_DIM + kb + k16 * 8;
            cpa16(bufB + dst, Whi_t + so);
            cpa16(bufB + 32768u + dst, Wlo_t + so);
        }
        cpa_commit();
    };

    // -------- warp/lane constants for ldmatrix --------
    const int mgrp  = wid >> 1;
    const int nhalf = wid & 1;
    const int j   = lane & 7;
    const int sub = lane >> 3;

    // A: two m16 tiles at rows mgrp*32 + {0,16}
    uint32_t a_base[2], a_xr[2];
    #pragma unroll
    for (int mt = 0; mt < 2; ++mt) {
        int row = mgrp * 32 + mt * 16 + j + (sub & 1) * 8;
        a_xr[mt]   = (uint32_t)((row & 7) * 16);
        a_base[mt] = (uint32_t)(row * 128) + (uint32_t)((sub >> 1) * 16);
    }
    // B: per n16 tile p: rows nhalf*128 + p*16 + (sub>>1)*8 + j, col (sub&1)*16
    const int b_row0 = nhalf * 128 + ((sub >> 1) ? 8 : 0) + j;
    const uint32_t b_xr_j  = 0;  // recomputed per p (row changes)
    (void)b_xr_j;

    float acc[2][16][4];
    #pragma unroll
    for (int mt = 0; mt < 2; ++mt)
        #pragma unroll
        for (int i = 0; i < 16; ++i)
            #pragma unroll
            for (int q = 0; q < 4; ++q) acc[mt][i][q] = 0.f;

    issue_chunk(0);

    for (int c = 0; c < NCHUNK; ++c) {
        const uint32_t stg = sb + OFF_STAGE0 + (uint32_t)(c & 1) * STAGE_BYTES;

        cpa_wait0();          // chunk c's A_raw + B arrived
        __syncthreads();

        // ---- split A_raw (fp32) -> bf16 hi/lo into this stage ----
        #pragma unroll
        for (int r = 0; r < 8; ++r) {
            int i4 = r * GTHREADS + tid;           // [0,2048)
            int m = i4 >> 4, k4 = i4 & 15;
            float4 v = *(const float4*)(smem + OFF_ARAW + i4 * 16);
            if (s_idx[m] < 0) v = make_float4(0.f, 0.f, 0.f, 0.f);
            uint2 h, l;
            split4(v, h, l);
            uint32_t off = swz((uint32_t)(m * 128 + k4 * 8));
            *(uint2*)((char*)smem + (stg - sb) + off) = h;
            *(uint2*)((char*)smem + (stg - sb) + 16384 + off) = l;
        }
        __syncthreads();      // A_raw consumed; stage A written

        if (c + 1 < NCHUNK) issue_chunk(c + 1);   // overlaps with compute below

        // ---- compute chunk c: 4 K16 steps ----
        const uint32_t Ahi_b = stg;
        const uint32_t Alo_b = stg + 16384u;
        const uint32_t Bhi_b = stg + 32768u;
        const uint32_t Blo_b = stg + 65536u;

        #pragma unroll
        for (int ks = 0; ks < 4; ++ks) {
            const uint32_t kbyte = (uint32_t)(ks * 32);
            uint32_t ah[2][4], al[2][4];
            #pragma unroll
            for (int mt = 0; mt < 2; ++mt) {
                uint32_t ao = (a_base[mt] + kbyte) ^ a_xr[mt];
                ldsm4(ah[mt][0], ah[mt][1], ah[mt][2], ah[mt][3], Ahi_b + ao);
                ldsm4(al[mt][0], al[mt][1], al[mt][2], al[mt][3], Alo_b + ao);
            }
            #pragma unroll
            for (int p = 0; p < 8; ++p) {
                int row = b_row0 + p * 16;
                uint32_t bxr = (uint32_t)((row & 7) * 16);
                uint32_t boff = ((uint32_t)(row * 128) + (uint32_t)((sub & 1) * 16) + kbyte) ^ bxr;
                uint32_t bh0, bh1, bh2, bh3, bl0, bl1, bl2, bl3;
                ldsm4(bh0, bh1, bh2, bh3, Bhi_b + boff);
                ldsm4(bl0, bl1, bl2, bl3, Blo_b + boff);
                #pragma unroll
                for (int mt = 0; mt < 2; ++mt) {
                    mma16816(acc[mt][2 * p],     ah[mt], bh0, bh1);
                    mma16816(acc[mt][2 * p + 1], ah[mt], bh2, bh3);
                    mma16816(acc[mt][2 * p],     ah[mt], bl0, bl1);
                    mma16816(acc[mt][2 * p + 1], ah[mt], bl2, bl3);
                    mma16816(acc[mt][2 * p],     al[mt], bh0, bh1);
                    mma16816(acc[mt][2 * p + 1], al[mt], bh2, bh3);
                }
            }
        }
        __syncthreads();      // stage consumed before it is refilled (c+2)
    }

    // ---- epilogue: bias + scatter-store ----
    const int colbase = nhalf * 128 + (lane & 3) * 2;
    #pragma unroll
    for (int mt = 0; mt < 2; ++mt) {
        const int r0 = mgrp * 32 + mt * 16 + (lane >> 2);
        const int g0 = s_idx[r0];
        const int g1 = s_idx[r0 + 8];
        #pragma unroll
        for (int nt = 0; nt < 16; ++nt) {
            const int col = colbase + nt * 8;
            const float bv0 = s_bias[col], bv1 = s_bias[col + 1];
            if (g0 >= 0) {
                float2 v0 = make_float2(acc[mt][nt][0] + bv0, acc[mt][nt][1] + bv1);
                *(float2*)(out + (size_t)g0 * OUT_DIM + col) = v0;
            }
            if (g1 >= 0) {
                float2 v1 = make_float2(acc[mt][nt][2] + bv0, acc[mt][nt][3] + bv1);
                *(float2*)(out + (size_t)g1 * OUT_DIM + col) = v1;
            }
        }
    }
}

// ============================================================================
// Launch
// ============================================================================
extern "C" void kernel_launch(void* const* d_in, const int* in_sizes, int n_in,
                              void* d_out, int out_size) {
    const float* x     = (const float*)d_in[0];
    const int*   types = (const int*)d_in[1];
    const float* W     = (const float*)d_in[2];
    const float* b     = (const float*)d_in[3];
    float*       out   = (float*)d_out;

    cudaFuncSetAttribute(typed_linear_gemm, cudaFuncAttributeMaxDynamicSharedMemorySize,
                         SMEM_BYTES);

    k_zero<<<1, 32>>>();
    k_wsplit<<<512, 256>>>(W);
    k_hist<<<16, 1024>>>(types);
    k_scan<<<1, 256>>>();
    k_scatter<<<16, 1024>>>(types);
    typed_linear_gemm<<<MAXTILES, GTHREADS, SMEM_BYTES>>>(x, b, out);
}

// round 6
// speedup vs baseline: 1.7660x; 1.3774x over previous
#include <cuda_runtime.h>
#include <cuda_fp16.h>
#include <cstdint>

// ============================================================================
// Problem constants
// ============================================================================
#define N_ROWS   65536
#define IN_DIM   256
#define OUT_DIM  256
#define NTYPES   8
#define BM       128                       // rows per GEMM tile
#define MAXTILES (N_ROWS / BM + NTYPES)    // 520
#define KC       64                        // K-chunk
#define NCHUNK   (IN_DIM / KC)             // 4
#define GTHREADS 256
#define HIST_BLOCKS 64

// SMEM layout (bytes):
//  [0]      s_idx[128]                  512B
//  [512]    s_bias[256]                 1KB
//  [2048]   A_raw fp32 staging          32KB
//  [34816]  stage0: Ah 16K | Bh 32K | Bl 32K = 80KB
//  [116736] stage1: 80KB
#define OFF_ARAW    2048
#define OFF_STAGE0  34816
#define STAGE_BYTES 81920
#define SMEM_BYTES  198656

// ============================================================================
// Device scratch
// ============================================================================
__device__ int g_counts[NTYPES];   // zero at start of each replay (self-resetting)
__device__ int g_cursor[NTYPES];   // zero at start of each replay (self-resetting)
__device__ int g_padstart[NTYPES];
__device__ int g_idx[MAXTILES * BM];
__device__ int g_tiletype[MAXTILES];
__device__ __align__(16) __half g_Whi[NTYPES * OUT_DIM * IN_DIM];
__device__ __align__(16) __half g_Wlo[NTYPES * OUT_DIM * IN_DIM];

// ============================================================================
// Helpers
// ============================================================================
__device__ __forceinline__ uint32_t smem_u32(const void* p) {
    uint32_t a;
    asm("{ .reg .u64 t; cvta.to.shared.u64 t, %1; cvt.u32.u64 %0, t; }" : "=r"(a) : "l"(p));
    return a;
}

__device__ __forceinline__ uint32_t swz(uint32_t off) { return off ^ ((off >> 3) & 0x70); }

__device__ __forceinline__ void cpa16(uint32_t dst, const void* src) {
    asm volatile("cp.async.cg.shared.global [%0], [%1], 16;" :: "r"(dst), "l"(src));
}
__device__ __forceinline__ void cpa_commit() {
    asm volatile("cp.async.commit_group;");
}
__device__ __forceinline__ void cpa_wait0() {
    asm volatile("cp.async.wait_group 0;" ::: "memory");
}

__device__ __forceinline__ void ldsm4(uint32_t* r, uint32_t addr) {
    asm volatile("ldmatrix.sync.aligned.m8n8.x4.shared.b16 {%0,%1,%2,%3}, [%4];"
                 : "=r"(r[0]), "=r"(r[1]), "=r"(r[2]), "=r"(r[3]) : "r"(addr));
}

__device__ __forceinline__ void mma16816(float* c, const uint32_t* a, uint32_t b0, uint32_t b1) {
    asm volatile("mma.sync.aligned.m16n8k16.row.col.f32.f16.f16.f32 "
                 "{%0,%1,%2,%3}, {%4,%5,%6,%7}, {%8,%9}, {%0,%1,%2,%3};"
                 : "+f"(c[0]), "+f"(c[1]), "+f"(c[2]), "+f"(c[3])
                 : "r"(a[0]), "r"(a[1]), "r"(a[2]), "r"(a[3]), "r"(b0), "r"(b1));
}

__device__ __forceinline__ uint32_t h2_as_u32(__half2 h) {
    return *reinterpret_cast<uint32_t*>(&h);
}

// ============================================================================
// k_prep1: blocks [0, HIST_BLOCKS) = type histogram; rest = W hi/lo split.
// (Independent work; no cross-block dependencies inside this kernel.)
// ============================================================================
__global__ void __launch_bounds__(256) k_prep1(const float* __restrict__ W,
                                               const int* __restrict__ types) {
    const int bid = blockIdx.x, tid = threadIdx.x;

    if (bid < HIST_BLOCKS) {
        __shared__ int c[NTYPES];
        if (tid < NTYPES) c[tid] = 0;
        __syncthreads();
        int i = bid * 256 + tid;                       // [0, 16384)
        int4 tv = *(const int4*)(types + i * 4);
        atomicAdd(&c[tv.x], 1);
        atomicAdd(&c[tv.y], 1);
        atomicAdd(&c[tv.z], 1);
        atomicAdd(&c[tv.w], 1);
        __syncthreads();
        if (tid < NTYPES) atomicAdd(&g_counts[tid], c[tid]);
        return;
    }

    // ---- W split: fp32 -> fp16 hi + fp16 lo (Whi + Wlo == W to ~2^-22) ----
    int i4 = (bid - HIST_BLOCKS) * 256 + tid;          // [0, 131072)
    float4 v = *(const float4*)(W + (size_t)i4 * 4);
    __half2 h01 = __floats2half2_rn(v.x, v.y);
    __half2 h23 = __floats2half2_rn(v.z, v.w);
    float2 f01 = __half22float2(h01), f23 = __half22float2(h23);
    __half2 l01 = __floats2half2_rn(v.x - f01.x, v.y - f01.y);
    __half2 l23 = __floats2half2_rn(v.z - f23.x, v.w - f23.y);
    *(uint2*)(g_Whi + (size_t)i4 * 4) = make_uint2(h2_as_u32(h01), h2_as_u32(h23));
    *(uint2*)(g_Wlo + (size_t)i4 * 4) = make_uint2(h2_as_u32(l01), h2_as_u32(l23));
}

// ============================================================================
// k_scan: prefix offsets, tile->type table, padded-slot marking
// ============================================================================
__global__ void k_scan() {
    __shared__ int s_start[NTYPES], s_tiles[NTYPES];
    int tid = threadIdx.x;
    if (tid == 0) {
        int off = 0;
        for (int t = 0; t < NTYPES; t++) {
            s_start[t] = off;
            g_padstart[t] = off;
            int tt = (g_counts[t] + BM - 1) / BM;
            s_tiles[t] = tt;
            off += tt * BM;
        }
    }
    __syncthreads();
    for (int tile = tid; tile < MAXTILES; tile += blockDim.x) {
        int ty = -1;
        int rb = tile * BM;
        for (int t = 0; t < NTYPES; t++)
            if (rb >= s_start[t] && rb < s_start[t] + s_tiles[t] * BM) ty = t;
        g_tiletype[tile] = ty;
    }
    for (int j = tid; j < NTYPES * BM; j += blockDim.x) {
        int t = j / BM, o = j % BM;
        int slot = g_counts[t] + o;
        if (slot < s_tiles[t] * BM) g_idx[s_start[t] + slot] = -1;
    }
}

// ============================================================================
// k_scatter: stable-ish scatter by type + self-reset of counters for replay
// ============================================================================
__global__ void __launch_bounds__(256) k_scatter(const int* __restrict__ types) {
    __shared__ int c[NTYPES], base[NTYPES];
    int tid = threadIdx.x;
    if (tid < NTYPES) c[tid] = 0;
    __syncthreads();
    int i = blockIdx.x * 256 + tid;                    // [0, 16384)
    int4 tv = *(const int4*)(types + i * 4);
    int p0 = atomicAdd(&c[tv.x], 1);
    int p1 = atomicAdd(&c[tv.y], 1);
    int p2 = atomicAdd(&c[tv.z], 1);
    int p3 = atomicAdd(&c[tv.w], 1);
    __syncthreads();
    if (tid < NTYPES) base[tid] = atomicAdd(&g_cursor[tid], c[tid]);
    __syncthreads();
    g_idx[g_padstart[tv.x] + base[tv.x] + p0] = i * 4;
    g_idx[g_padstart[tv.y] + base[tv.y] + p1] = i * 4 + 1;
    g_idx[g_padstart[tv.z] + base[tv.z] + p2] = i * 4 + 2;
    g_idx[g_padstart[tv.w] + base[tv.w] + p3] = i * 4 + 3;
    // self-reset for the next graph replay (g_counts consumed by prior k_scan;
    // g_cursor consumed above). Each block removes exactly its contribution.
    if (tid < NTYPES) {
        atomicSub(&g_counts[tid], c[tid]);
        atomicSub(&g_cursor[tid], c[tid]);
    }
}

// ============================================================================
// Grouped GEMM: per tile, D[128,256] = gather(x) * W[t]^T + b[t]
// fp16 2-term: xh*Whi + xh*Wlo.  8 warps in 2(M)x4(N); warp tile 64x64.
// cp.async double-buffered stages; one commit group per chunk.
// ============================================================================
__global__ void __launch_bounds__(GTHREADS, 1)
typed_linear_gemm(const float* __restrict__ x, const float* __restrict__ b,
                  float* __restrict__ out) {
    extern __shared__ char smem[];
    const int tile = blockIdx.x;
    const int t = g_tiletype[tile];
    if (t < 0) return;

    const int tid  = threadIdx.x;
    const int wid  = tid >> 5;
    const int lane = tid & 31;
    const uint32_t sb = smem_u32(smem);

    int*   s_idx  = (int*)smem;
    float* s_bias = (float*)(smem + 512);

    if (tid < BM) s_idx[tid] = g_idx[tile * BM + tid];
    s_bias[tid] = b[t * OUT_DIM + tid];
    __syncthreads();

    const __half* Whi_t = g_Whi + (size_t)t * OUT_DIM * IN_DIM;
    const __half* Wlo_t = g_Wlo + (size_t)t * OUT_DIM * IN_DIM;

    // Per chunk: A raw (128x64 fp32 -> 2048x16B, 8/thread) + B hi/lo
    // (256x64 fp16 = 1024x16B each); all in ONE commit group.
    auto issue_chunk = [&](int c) {
        const int kb = c * KC;
        #pragma unroll
        for (int r = 0; r < 8; ++r) {
            int i16 = r * GTHREADS + tid;
            int m = i16 >> 4, k16 = i16 & 15;
            int g = s_idx[m];
            const float* src = x + (size_t)(g < 0 ? 0 : g) * IN_DIM + kb + k16 * 4;
            cpa16(sb + OFF_ARAW + (uint32_t)(i16 * 16), src);
        }
        const uint32_t bufB = sb + OFF_STAGE0 + (uint32_t)(c & 1) * STAGE_BYTES + 16384u;
        #pragma unroll
        for (int r = 0; r < 4; ++r) {
            int i16 = r * GTHREADS + tid;          // [0,1024)
            int n = i16 >> 2, k16 = i16 & 3;
            // swizzle computed PER 16B granule (swz(off)+16 != swz(off+16)!)
            uint32_t raw = (uint32_t)(n * 128 + k16 * 32);
            uint32_t d0 = swz(raw);
            uint32_t d1 = swz(raw + 16);
            size_t so = (size_t)n * IN_DIM + kb + k16 * 16;
            cpa16(bufB + d0, Whi_t + so);
            cpa16(bufB + d1, Whi_t + so + 8);
            cpa16(bufB + 32768u + d0, Wlo_t + so);
            cpa16(bufB + 32768u + d1, Wlo_t + so + 8);
        }
        cpa_commit();
    };

    // -------- warp/lane constants for ldmatrix --------
    const int mgrp = wid >> 2;      // rows [64*mgrp, +64)
    const int nq   = wid & 3;       // cols [64*nq, +64)
    const int j = lane & 7, sub = lane >> 3;

    uint32_t a_base[4], a_xr[4], b_base[4], b_xr[4];
    #pragma unroll
    for (int mt = 0; mt < 4; ++mt) {
        int row = mgrp * 64 + mt * 16 + j + (sub & 1) * 8;
        a_xr[mt]   = (uint32_t)((row & 7) * 16);
        a_base[mt] = (uint32_t)(row * 128) + (uint32_t)((sub >> 1) * 16);
    }
    #pragma unroll
    for (int nt = 0; nt < 4; ++nt) {
        int row = nq * 64 + nt * 16 + (sub >> 1) * 8 + j;
        b_xr[nt]   = (uint32_t)((row & 7) * 16);
        b_base[nt] = (uint32_t)(row * 128) + (uint32_t)((sub & 1) * 16);
    }

    float acc[4][8][4];
    #pragma unroll
    for (int mt = 0; mt < 4; ++mt)
        #pragma unroll
        for (int i = 0; i < 8; ++i)
            #pragma unroll
            for (int q = 0; q < 4; ++q) acc[mt][i][q] = 0.f;

    issue_chunk(0);

    for (int c = 0; c < NCHUNK; ++c) {
        const uint32_t stg = sb + OFF_STAGE0 + (uint32_t)(c & 1) * STAGE_BYTES;
        const uint32_t Ah = stg, Bh = stg + 16384u, Bl = stg + 49152u;

        cpa_wait0();              // chunk c's A_raw + B hi/lo arrived
        __syncthreads();          // + all warps done computing chunk c-1

        // ---- convert A_raw fp32 -> fp16 into stage c ----
        #pragma unroll
        for (int r = 0; r < 8; ++r) {
            int i4 = r * GTHREADS + tid;           // [0,2048)
            int m = i4 >> 4, k4 = i4 & 15;
            float4 v = *(const float4*)(smem + OFF_ARAW + i4 * 16);
            if (s_idx[m] < 0) v = make_float4(0.f, 0.f, 0.f, 0.f);
            __half2 h01 = __floats2half2_rn(v.x, v.y);
            __half2 h23 = __floats2half2_rn(v.z, v.w);
            *(uint2*)(smem + (Ah - sb) + swz((uint32_t)(m * 128 + k4 * 8))) =
                make_uint2(h2_as_u32(h01), h2_as_u32(h23));
        }
        __syncthreads();          // A_raw consumed; stage A visible to all warps

        if (c + 1 < NCHUNK) issue_chunk(c + 1);   // overlaps with compute below

        // ---- compute chunk c ----
        #pragma unroll
        for (int ks = 0; ks < 4; ++ks) {
            const uint32_t kb = (uint32_t)(ks * 32);
            uint32_t ah[4][4], bhr[4][4], blr[4][4];
            #pragma unroll
            for (int mt = 0; mt < 4; ++mt)
                ldsm4(ah[mt], Ah + ((a_base[mt] + kb) ^ a_xr[mt]));
            #pragma unroll
            for (int nt = 0; nt < 4; ++nt) {
                uint32_t off = (b_base[nt] + kb) ^ b_xr[nt];
                ldsm4(bhr[nt], Bh + off);
                ldsm4(blr[nt], Bl + off);
            }
            #pragma unroll
            for (int nt = 0; nt < 4; ++nt)
                #pragma unroll
                for (int mt = 0; mt < 4; ++mt) {
                    mma16816(acc[mt][2 * nt],     ah[mt], bhr[nt][0], bhr[nt][1]);
                    mma16816(acc[mt][2 * nt + 1], ah[mt], bhr[nt][2], bhr[nt][3]);
                }
            #pragma unroll
            for (int nt = 0; nt < 4; ++nt)
                #pragma unroll
                for (int mt = 0; mt < 4; ++mt) {
                    mma16816(acc[mt][2 * nt],     ah[mt], blr[nt][0], blr[nt][1]);
                    mma16816(acc[mt][2 * nt + 1], ah[mt], blr[nt][2], blr[nt][3]);
                }
        }
    }

    // ---- epilogue: bias + scatter-store ----
    #pragma unroll
    for (int mt = 0; mt < 4; ++mt) {
        const int r0 = mgrp * 64 + mt * 16 + (lane >> 2);
        const int g0 = s_idx[r0];
        const int g1 = s_idx[r0 + 8];
        #pragma unroll
        for (int n8 = 0; n8 < 8; ++n8) {
            const int col = nq * 64 + n8 * 8 + (lane & 3) * 2;
            const float bv0 = s_bias[col], bv1 = s_bias[col + 1];
            if (g0 >= 0) {
                float2 v0 = make_float2(acc[mt][n8][0] + bv0, acc[mt][n8][1] + bv1);
                *(float2*)(out + (size_t)g0 * OUT_DIM + col) = v0;
            }
            if (g1 >= 0) {
                float2 v1 = make_float2(acc[mt][n8][2] + bv0, acc[mt][n8][3] + bv1);
                *(float2*)(out + (size_t)g1 * OUT_DIM + col) = v1;
            }
        }
    }
}

// ============================================================================
// Launch
// ============================================================================
extern "C" void kernel_launch(void* const* d_in, const int* in_sizes, int n_in,
                              void* d_out, int out_size) {
    const float* x     = (const float*)d_in[0];
    const int*   types = (const int*)d_in[1];
    const float* W     = (const float*)d_in[2];
    const float* b     = (const float*)d_in[3];
    float*       out   = (float*)d_out;

    cudaFuncSetAttribute(typed_linear_gemm, cudaFuncAttributeMaxDynamicSharedMemorySize,
                         SMEM_BYTES);

    k_prep1<<<HIST_BLOCKS + 512, 256>>>(W, types);
    k_scan<<<1, 256>>>();
    k_scatter<<<HIST_BLOCKS, 256>>>(types);
    typed_linear_gemm<<<MAXTILES, GTHREADS, SMEM_BYTES>>>(x, b, out);
}

// round 7
// speedup vs baseline: 1.8720x; 1.0600x over previous
#include <cuda_runtime.h>
#include <cuda_fp16.h>
#include <cstdint>

// ============================================================================
// Problem constants
// ============================================================================
#define N_ROWS   65536
#define IN_DIM   256
#define OUT_DIM  256
#define NTYPES   8
#define BM       128                       // rows per block tile
#define BN       128                       // cols per block tile (OUT split in 2)
#define MAXTILES (N_ROWS / BM + NTYPES)    // 520 row-tiles
#define KC       64                        // K-chunk
#define NCHUNK   (IN_DIM / KC)             // 4
#define GTHREADS 256
#define HIST_BLOCKS 64

// SMEM layout (bytes):
//  [0]      s_idx[128]     512B
//  [512]    s_bias[128]    512B
//  [1024]   stage0: Ah 16K | Bh 16K | Bl 16K = 48K
//  [50176]  stage1: 48K
#define OFF_STAGE0  1024
#define STAGE_BYTES 49152
#define SMEM_BYTES  99328

// ============================================================================
// Device scratch
// ============================================================================
__device__ int g_counts[NTYPES];   // self-resetting across graph replays
__device__ int g_cursor[NTYPES];   // self-resetting across graph replays
__device__ int g_padstart[NTYPES];
__device__ int g_idx[MAXTILES * BM];
__device__ int g_tiletype[MAXTILES];
__device__ __align__(16) __half g_Whi[NTYPES * OUT_DIM * IN_DIM];
__device__ __align__(16) __half g_Wlo[NTYPES * OUT_DIM * IN_DIM];

// ============================================================================
// Helpers
// ============================================================================
__device__ __forceinline__ uint32_t smem_u32(const void* p) {
    uint32_t a;
    asm("{ .reg .u64 t; cvta.to.shared.u64 t, %1; cvt.u32.u64 %0, t; }" : "=r"(a) : "l"(p));
    return a;
}

__device__ __forceinline__ uint32_t swz(uint32_t off) { return off ^ ((off >> 3) & 0x70); }

__device__ __forceinline__ void cpa16(uint32_t dst, const void* src) {
    asm volatile("cp.async.cg.shared.global [%0], [%1], 16;" :: "r"(dst), "l"(src));
}
__device__ __forceinline__ void cpa_commit() {
    asm volatile("cp.async.commit_group;");
}
__device__ __forceinline__ void cpa_wait0() {
    asm volatile("cp.async.wait_group 0;" ::: "memory");
}

__device__ __forceinline__ void ldsm4(uint32_t* r, uint32_t addr) {
    asm volatile("ldmatrix.sync.aligned.m8n8.x4.shared.b16 {%0,%1,%2,%3}, [%4];"
                 : "=r"(r[0]), "=r"(r[1]), "=r"(r[2]), "=r"(r[3]) : "r"(addr));
}

__device__ __forceinline__ void mma16816(float* c, const uint32_t* a, uint32_t b0, uint32_t b1) {
    asm volatile("mma.sync.aligned.m16n8k16.row.col.f32.f16.f16.f32 "
                 "{%0,%1,%2,%3}, {%4,%5,%6,%7}, {%8,%9}, {%0,%1,%2,%3};"
                 : "+f"(c[0]), "+f"(c[1]), "+f"(c[2]), "+f"(c[3])
                 : "r"(a[0]), "r"(a[1]), "r"(a[2]), "r"(a[3]), "r"(b0), "r"(b1));
}

__device__ __forceinline__ uint32_t h2_as_u32(__half2 h) {
    return *reinterpret_cast<uint32_t*>(&h);
}

// ============================================================================
// k_prep1: blocks [0, HIST_BLOCKS) = type histogram; rest = W hi/lo split.
// ============================================================================
__global__ void __launch_bounds__(256) k_prep1(const float* __restrict__ W,
                                               const int* __restrict__ types) {
    const int bid = blockIdx.x, tid = threadIdx.x;

    if (bid < HIST_BLOCKS) {
        __shared__ int c[NTYPES];
        if (tid < NTYPES) c[tid] = 0;
        __syncthreads();
        int i = bid * 256 + tid;                       // [0, 16384)
        int4 tv = *(const int4*)(types + i * 4);
        atomicAdd(&c[tv.x], 1);
        atomicAdd(&c[tv.y], 1);
        atomicAdd(&c[tv.z], 1);
        atomicAdd(&c[tv.w], 1);
        __syncthreads();
        if (tid < NTYPES) atomicAdd(&g_counts[tid], c[tid]);
        return;
    }

    // ---- W split: fp32 -> fp16 hi + fp16 lo (Whi + Wlo == W to ~2^-22) ----
    int i4 = (bid - HIST_BLOCKS) * 256 + tid;          // [0, 131072)
    float4 v = *(const float4*)(W + (size_t)i4 * 4);
    __half2 h01 = __floats2half2_rn(v.x, v.y);
    __half2 h23 = __floats2half2_rn(v.z, v.w);
    float2 f01 = __half22float2(h01), f23 = __half22float2(h23);
    __half2 l01 = __floats2half2_rn(v.x - f01.x, v.y - f01.y);
    __half2 l23 = __floats2half2_rn(v.z - f23.x, v.w - f23.y);
    *(uint2*)(g_Whi + (size_t)i4 * 4) = make_uint2(h2_as_u32(h01), h2_as_u32(h23));
    *(uint2*)(g_Wlo + (size_t)i4 * 4) = make_uint2(h2_as_u32(l01), h2_as_u32(l23));
}

// ============================================================================
// k_scan: prefix offsets, tile->type table, padded-slot marking
// ============================================================================
__global__ void k_scan() {
    __shared__ int s_start[NTYPES], s_tiles[NTYPES];
    int tid = threadIdx.x;
    if (tid == 0) {
        int off = 0;
        for (int t = 0; t < NTYPES; t++) {
            s_start[t] = off;
            g_padstart[t] = off;
            int tt = (g_counts[t] + BM - 1) / BM;
            s_tiles[t] = tt;
            off += tt * BM;
        }
    }
    __syncthreads();
    for (int tile = tid; tile < MAXTILES; tile += blockDim.x) {
        int ty = -1;
        int rb = tile * BM;
        for (int t = 0; t < NTYPES; t++)
            if (rb >= s_start[t] && rb < s_start[t] + s_tiles[t] * BM) ty = t;
        g_tiletype[tile] = ty;
    }
    for (int j = tid; j < NTYPES * BM; j += blockDim.x) {
        int t = j / BM, o = j % BM;
        int slot = g_counts[t] + o;
        if (slot < s_tiles[t] * BM) g_idx[s_start[t] + slot] = -1;
    }
}

// ============================================================================
// k_scatter: scatter rows by type + self-reset of counters for graph replay
// ============================================================================
__global__ void __launch_bounds__(256) k_scatter(const int* __restrict__ types) {
    __shared__ int c[NTYPES], base[NTYPES];
    int tid = threadIdx.x;
    if (tid < NTYPES) c[tid] = 0;
    __syncthreads();
    int i = blockIdx.x * 256 + tid;                    // [0, 16384)
    int4 tv = *(const int4*)(types + i * 4);
    int p0 = atomicAdd(&c[tv.x], 1);
    int p1 = atomicAdd(&c[tv.y], 1);
    int p2 = atomicAdd(&c[tv.z], 1);
    int p3 = atomicAdd(&c[tv.w], 1);
    __syncthreads();
    if (tid < NTYPES) base[tid] = atomicAdd(&g_cursor[tid], c[tid]);
    __syncthreads();
    g_idx[g_padstart[tv.x] + base[tv.x] + p0] = i * 4;
    g_idx[g_padstart[tv.y] + base[tv.y] + p1] = i * 4 + 1;
    g_idx[g_padstart[tv.z] + base[tv.z] + p2] = i * 4 + 2;
    g_idx[g_padstart[tv.w] + base[tv.w] + p3] = i * 4 + 3;
    if (tid < NTYPES) {
        atomicSub(&g_counts[tid], c[tid]);
        atomicSub(&g_cursor[tid], c[tid]);
    }
}

// ============================================================================
// Grouped GEMM: block = (row-tile, N-half). D[128,128] = gather(x)*Wslice^T + b
// fp16 2-term: xh*Whi + xh*Wlo.  8 warps in 2(M)x4(N); warp tile 64x32.
// 64 fp32 acc/thread -> 2 CTAs/SM. B via cp.async; A via LDG+convert+STS.
// ============================================================================
__global__ void __launch_bounds__(GTHREADS, 2)
typed_linear_gemm(const float* __restrict__ x, const float* __restrict__ b,
                  float* __restrict__ out) {
    extern __shared__ char smem[];
    const int tile  = blockIdx.x >> 1;
    const int nside = blockIdx.x & 1;
    const int t = g_tiletype[tile];
    if (t < 0) return;

    const int tid  = threadIdx.x;
    const int wid  = tid >> 5;
    const int lane = tid & 31;
    const uint32_t sb = smem_u32(smem);

    int*   s_idx  = (int*)smem;
    float* s_bias = (float*)(smem + 512);

    if (tid < BM) s_idx[tid] = g_idx[tile * BM + tid];
    if (tid < BN) s_bias[tid] = b[t * OUT_DIM + nside * BN + tid];
    __syncthreads();

    const __half* Whi_t = g_Whi + ((size_t)t * OUT_DIM + nside * BN) * IN_DIM;
    const __half* Wlo_t = g_Wlo + ((size_t)t * OUT_DIM + nside * BN) * IN_DIM;

    // B hi/lo: 128 rows x 64 fp16 (128B/row) = 1024 x 16B each; 4+4 per thread
    auto issueB = [&](int c) {
        const int kb = c * KC;
        const uint32_t bufB = sb + OFF_STAGE0 + (uint32_t)(c & 1) * STAGE_BYTES + 16384u;
        #pragma unroll
        for (int r = 0; r < 4; ++r) {
            int i16 = r * GTHREADS + tid;          // [0,1024)
            int n = i16 >> 3, k16 = i16 & 7;
            uint32_t d = swz((uint32_t)(n * 128 + k16 * 16));
            size_t so = (size_t)n * IN_DIM + kb + k16 * 8;
            cpa16(bufB + d, Whi_t + so);
            cpa16(bufB + 16384u + d, Wlo_t + so);
        }
        cpa_commit();
    };

    // A: 128 rows x 64 fp32 gathered -> fp16 -> SW128 smem; 8 float4/thread
    auto loadA = [&](int c) {
        const int kb = c * KC;
        const uint32_t bufA = sb + OFF_STAGE0 + (uint32_t)(c & 1) * STAGE_BYTES;
        #pragma unroll
        for (int h = 0; h < 2; ++h) {
            float4 v[4];
            #pragma unroll
            for (int r = 0; r < 4; ++r) {
                int i4 = (h * 4 + r) * GTHREADS + tid;   // [0,2048)
                int m = i4 >> 4, k4 = i4 & 15;
                int g = s_idx[m];
                v[r] = (g >= 0) ? *(const float4*)(x + (size_t)g * IN_DIM + kb + k4 * 4)
                                : make_float4(0.f, 0.f, 0.f, 0.f);
            }
            #pragma unroll
            for (int r = 0; r < 4; ++r) {
                int i4 = (h * 4 + r) * GTHREADS + tid;
                int m = i4 >> 4, k4 = i4 & 15;
                __half2 h01 = __floats2half2_rn(v[r].x, v[r].y);
                __half2 h23 = __floats2half2_rn(v[r].z, v[r].w);
                *(uint2*)(smem + (bufA - sb) + swz((uint32_t)(m * 128 + k4 * 8))) =
                    make_uint2(h2_as_u32(h01), h2_as_u32(h23));
            }
        }
    };

    // -------- warp/lane constants for ldmatrix --------
    const int mgrp = wid >> 2;      // rows [64*mgrp, +64)
    const int nq   = wid & 3;       // cols [32*nq, +32) within the 128-col tile
    const int j = lane & 7, sub = lane >> 3;

    uint32_t a_base[4], a_xr[4], b_base[2], b_xr[2];
    #pragma unroll
    for (int mt = 0; mt < 4; ++mt) {
        int row = mgrp * 64 + mt * 16 + j + (sub & 1) * 8;
        a_xr[mt]   = (uint32_t)((row & 7) * 16);
        a_base[mt] = (uint32_t)(row * 128) + (uint32_t)((sub >> 1) * 16);
    }
    #pragma unroll
    for (int nt = 0; nt < 2; ++nt) {
        int row = nq * 32 + nt * 16 + (sub >> 1) * 8 + j;
        b_xr[nt]   = (uint32_t)((row & 7) * 16);
        b_base[nt] = (uint32_t)(row * 128) + (uint32_t)((sub & 1) * 16);
    }

    float acc[4][4][4];   // [mt][n8][quad]
    #pragma unroll
    for (int mt = 0; mt < 4; ++mt)
        #pragma unroll
        for (int i = 0; i < 4; ++i)
            #pragma unroll
            for (int q = 0; q < 4; ++q) acc[mt][i][q] = 0.f;

    issueB(0);
    loadA(0);

    for (int c = 0; c < NCHUNK; ++c) {
        const uint32_t stg = sb + OFF_STAGE0 + (uint32_t)(c & 1) * STAGE_BYTES;
        const uint32_t Ah = stg, Bh = stg + 16384u, Bl = stg + 32768u;

        cpa_wait0();              // B(c) arrived
        __syncthreads();          // all warps done with stage (c+1)&1 (chunk c-1)

        if (c + 1 < NCHUNK) issueB(c + 1);    // safe: past the barrier

        // ---- compute chunk c: 4 K16 steps ----
        #pragma unroll
        for (int ks = 0; ks < 4; ++ks) {
            const uint32_t kb = (uint32_t)(ks * 32);
            uint32_t ah[4][4], bhr[2][4], blr[2][4];
            #pragma unroll
            for (int mt = 0; mt < 4; ++mt)
                ldsm4(ah[mt], Ah + ((a_base[mt] + kb) ^ a_xr[mt]));
            #pragma unroll
            for (int nt = 0; nt < 2; ++nt) {
                uint32_t off = (b_base[nt] + kb) ^ b_xr[nt];
                ldsm4(bhr[nt], Bh + off);
                ldsm4(blr[nt], Bl + off);
            }
            #pragma unroll
            for (int nt = 0; nt < 2; ++nt)
                #pragma unroll
                for (int mt = 0; mt < 4; ++mt) {
                    mma16816(acc[mt][2 * nt],     ah[mt], bhr[nt][0], bhr[nt][1]);
                    mma16816(acc[mt][2 * nt + 1], ah[mt], bhr[nt][2], bhr[nt][3]);
                }
            #pragma unroll
            for (int nt = 0; nt < 2; ++nt)
                #pragma unroll
                for (int mt = 0; mt < 4; ++mt) {
                    mma16816(acc[mt][2 * nt],     ah[mt], blr[nt][0], blr[nt][1]);
                    mma16816(acc[mt][2 * nt + 1], ah[mt], blr[nt][2], blr[nt][3]);
                }
        }

        if (c + 1 < NCHUNK) loadA(c + 1);     // writes stage (c+1)&1; ordered by
                                              // next iteration's barrier
    }

    // ---- epilogue: bias + scatter-store ----
    #pragma unroll
    for (int mt = 0; mt < 4; ++mt) {
        const int r0 = mgrp * 64 + mt * 16 + (lane >> 2);
        const int g0 = s_idx[r0];
        const int g1 = s_idx[r0 + 8];
        #pragma unroll
        for (int n8 = 0; n8 < 4; ++n8) {
            const int lcol = nq * 32 + n8 * 8 + (lane & 3) * 2;
            const int col  = nside * BN + lcol;
            const float bv0 = s_bias[lcol], bv1 = s_bias[lcol + 1];
            if (g0 >= 0) {
                float2 v0 = make_float2(acc[mt][n8][0] + bv0, acc[mt][n8][1] + bv1);
                *(float2*)(out + (size_t)g0 * OUT_DIM + col) = v0;
            }
            if (g1 >= 0) {
                float2 v1 = make_float2(acc[mt][n8][2] + bv0, acc[mt][n8][3] + bv1);
                *(float2*)(out + (size_t)g1 * OUT_DIM + col) = v1;
            }
        }
    }
}

// ============================================================================
// Launch
// ============================================================================
extern "C" void kernel_launch(void* const* d_in, const int* in_sizes, int n_in,
                              void* d_out, int out_size) {
    const float* x     = (const float*)d_in[0];
    const int*   types = (const int*)d_in[1];
    const float* W     = (const float*)d_in[2];
    const float* b     = (const float*)d_in[3];
    float*       out   = (float*)d_out;

    cudaFuncSetAttribute(typed_linear_gemm, cudaFuncAttributeMaxDynamicSharedMemorySize,
                         SMEM_BYTES);

    k_prep1<<<HIST_BLOCKS + 512, 256>>>(W, types);
    k_scan<<<1, 256>>>();
    k_scatter<<<HIST_BLOCKS, 256>>>(types);
    typed_linear_gemm<<<MAXTILES * 2, GTHREADS, SMEM_BYTES>>>(x, b, out);
}

// round 8
// speedup vs baseline: 2.2188x; 1.1853x over previous
#include <cuda_runtime.h>
#include <cuda_fp16.h>
#include <cstdint>

// ============================================================================
// Problem constants
// ============================================================================
#define N_ROWS   65536
#define IN_DIM   256
#define OUT_DIM  256
#define NTYPES   8
#define BM       128                       // rows per block tile
#define BN       128                       // cols per block tile (OUT split in 2)
#define MAXTILES (N_ROWS / BM + NTYPES)    // 520 row-tiles
#define KC       64                        // K-chunk
#define NCHUNK   (IN_DIM / KC)             // 4
#define GTHREADS 256
#define HIST_BLOCKS 64

// SMEM layout (bytes):
//  [0]      s_idx[128]     512B
//  [512]    s_bias[128]    512B
//  [1024]   stage0: Ah 16K | Bh 16K = 32K
//  [33792]  stage1: 32K
#define OFF_STAGE0  1024
#define STAGE_BYTES 32768
#define SMEM_BYTES  66560

// ============================================================================
// Device scratch
// ============================================================================
__device__ int g_counts[NTYPES];   // self-resetting across graph replays
__device__ int g_cursor[NTYPES];   // self-resetting across graph replays
__device__ int g_padstart[NTYPES];
__device__ int g_idx[MAXTILES * BM];
__device__ int g_tiletype[MAXTILES];
__device__ __align__(16) __half g_Wh[NTYPES * OUT_DIM * IN_DIM];

// ============================================================================
// Helpers
// ============================================================================
__device__ __forceinline__ uint32_t smem_u32(const void* p) {
    uint32_t a;
    asm("{ .reg .u64 t; cvta.to.shared.u64 t, %1; cvt.u32.u64 %0, t; }" : "=r"(a) : "l"(p));
    return a;
}

__device__ __forceinline__ uint32_t swz(uint32_t off) { return off ^ ((off >> 3) & 0x70); }

__device__ __forceinline__ void cpa16(uint32_t dst, const void* src) {
    asm volatile("cp.async.cg.shared.global [%0], [%1], 16;" :: "r"(dst), "l"(src));
}
__device__ __forceinline__ void cpa_commit() {
    asm volatile("cp.async.commit_group;");
}
__device__ __forceinline__ void cpa_wait0() {
    asm volatile("cp.async.wait_group 0;" ::: "memory");
}

__device__ __forceinline__ void ldsm4(uint32_t* r, uint32_t addr) {
    asm volatile("ldmatrix.sync.aligned.m8n8.x4.shared.b16 {%0,%1,%2,%3}, [%4];"
                 : "=r"(r[0]), "=r"(r[1]), "=r"(r[2]), "=r"(r[3]) : "r"(addr));
}

__device__ __forceinline__ void mma16816(float* c, const uint32_t* a, uint32_t b0, uint32_t b1) {
    asm volatile("mma.sync.aligned.m16n8k16.row.col.f32.f16.f16.f32 "
                 "{%0,%1,%2,%3}, {%4,%5,%6,%7}, {%8,%9}, {%0,%1,%2,%3};"
                 : "+f"(c[0]), "+f"(c[1]), "+f"(c[2]), "+f"(c[3])
                 : "r"(a[0]), "r"(a[1]), "r"(a[2]), "r"(a[3]), "r"(b0), "r"(b1));
}

__device__ __forceinline__ uint32_t h2_as_u32(__half2 h) {
    return *reinterpret_cast<uint32_t*>(&h);
}

__device__ __forceinline__ void stcs2(float* p, float2 v) {
    asm volatile("st.global.cs.v2.f32 [%0], {%1, %2};" :: "l"(p), "f"(v.x), "f"(v.y));
}

// ============================================================================
// k_prep1: blocks [0, HIST_BLOCKS) = type histogram; rest = W -> fp16.
// ============================================================================
__global__ void __launch_bounds__(256) k_prep1(const float* __restrict__ W,
                                               const int* __restrict__ types) {
    const int bid = blockIdx.x, tid = threadIdx.x;

    if (bid < HIST_BLOCKS) {
        __shared__ int c[NTYPES];
        if (tid < NTYPES) c[tid] = 0;
        __syncthreads();
        int i = bid * 256 + tid;                       // [0, 16384)
        int4 tv = *(const int4*)(types + i * 4);
        atomicAdd(&c[tv.x], 1);
        atomicAdd(&c[tv.y], 1);
        atomicAdd(&c[tv.z], 1);
        atomicAdd(&c[tv.w], 1);
        __syncthreads();
        if (tid < NTYPES) atomicAdd(&g_counts[tid], c[tid]);
        return;
    }

    // ---- W convert: fp32 -> fp16 (single term) ----
    int i4 = (bid - HIST_BLOCKS) * 256 + tid;          // [0, 131072)
    float4 v = *(const float4*)(W + (size_t)i4 * 4);
    __half2 h01 = __floats2half2_rn(v.x, v.y);
    __half2 h23 = __floats2half2_rn(v.z, v.w);
    *(uint2*)(g_Wh + (size_t)i4 * 4) = make_uint2(h2_as_u32(h01), h2_as_u32(h23));
}

// ============================================================================
// k_scan: prefix offsets, tile->type table, padded-slot marking
// ============================================================================
__global__ void k_scan() {
    __shared__ int s_start[NTYPES], s_tiles[NTYPES];
    int tid = threadIdx.x;
    if (tid == 0) {
        int off = 0;
        for (int t = 0; t < NTYPES; t++) {
            s_start[t] = off;
            g_padstart[t] = off;
            int tt = (g_counts[t] + BM - 1) / BM;
            s_tiles[t] = tt;
            off += tt * BM;
        }
    }
    __syncthreads();
    for (int tile = tid; tile < MAXTILES; tile += blockDim.x) {
        int ty = -1;
        int rb = tile * BM;
        for (int t = 0; t < NTYPES; t++)
            if (rb >= s_start[t] && rb < s_start[t] + s_tiles[t] * BM) ty = t;
        g_tiletype[tile] = ty;
    }
    for (int j = tid; j < NTYPES * BM; j += blockDim.x) {
        int t = j / BM, o = j % BM;
        int slot = g_counts[t] + o;
        if (slot < s_tiles[t] * BM) g_idx[s_start[t] + slot] = -1;
    }
}

// ============================================================================
// k_scatter: scatter rows by type + self-reset of counters for graph replay
// ============================================================================
__global__ void __launch_bounds__(256) k_scatter(const int* __restrict__ types) {
    __shared__ int c[NTYPES], base[NTYPES];
    int tid = threadIdx.x;
    if (tid < NTYPES) c[tid] = 0;
    __syncthreads();
    int i = blockIdx.x * 256 + tid;                    // [0, 16384)
    int4 tv = *(const int4*)(types + i * 4);
    int p0 = atomicAdd(&c[tv.x], 1);
    int p1 = atomicAdd(&c[tv.y], 1);
    int p2 = atomicAdd(&c[tv.z], 1);
    int p3 = atomicAdd(&c[tv.w], 1);
    __syncthreads();
    if (tid < NTYPES) base[tid] = atomicAdd(&g_cursor[tid], c[tid]);
    __syncthreads();
    g_idx[g_padstart[tv.x] + base[tv.x] + p0] = i * 4;
    g_idx[g_padstart[tv.y] + base[tv.y] + p1] = i * 4 + 1;
    g_idx[g_padstart[tv.z] + base[tv.z] + p2] = i * 4 + 2;
    g_idx[g_padstart[tv.w] + base[tv.w] + p3] = i * 4 + 3;
    if (tid < NTYPES) {
        atomicSub(&g_counts[tid], c[tid]);
        atomicSub(&g_cursor[tid], c[tid]);
    }
}

// ============================================================================
// Grouped GEMM: block = (row-tile, N-half). D[128,128] = gather(x)*Wslice^T + b
// Single-term fp16: xh * Wh.  8 warps in 2(M)x4(N); warp tile 64x32.
// 64 fp32 acc/thread -> 2 CTAs/SM. B via cp.async; A via LDG+convert+STS.
// ============================================================================
__global__ void __launch_bounds__(GTHREADS, 2)
typed_linear_gemm(const float* __restrict__ x, const float* __restrict__ b,
                  float* __restrict__ out) {
    extern __shared__ char smem[];
    const int tile  = blockIdx.x >> 1;
    const int nside = blockIdx.x & 1;
    const int t = g_tiletype[tile];
    if (t < 0) return;

    const int tid  = threadIdx.x;
    const int wid  = tid >> 5;
    const int lane = tid & 31;
    const uint32_t sb = smem_u32(smem);

    int*   s_idx  = (int*)smem;
    float* s_bias = (float*)(smem + 512);

    if (tid < BM) s_idx[tid] = g_idx[tile * BM + tid];
    if (tid < BN) s_bias[tid] = b[t * OUT_DIM + nside * BN + tid];
    __syncthreads();

    const __half* Wh_t = g_Wh + ((size_t)t * OUT_DIM + nside * BN) * IN_DIM;

    // B: 128 rows x 64 fp16 (128B/row) = 1024 x 16B; 4 cpa16 per thread
    auto issueB = [&](int c) {
        const int kb = c * KC;
        const uint32_t bufB = sb + OFF_STAGE0 + (uint32_t)(c & 1) * STAGE_BYTES + 16384u;
        #pragma unroll
        for (int r = 0; r < 4; ++r) {
            int i16 = r * GTHREADS + tid;          // [0,1024)
            int n = i16 >> 3, k16 = i16 & 7;
            uint32_t d = swz((uint32_t)(n * 128 + k16 * 16));
            cpa16(bufB + d, Wh_t + (size_t)n * IN_DIM + kb + k16 * 8);
        }
        cpa_commit();
    };

    // A: 128 rows x 64 fp32 gathered -> fp16 -> SW128 smem; 8 float4/thread
    auto loadA = [&](int c) {
        const int kb = c * KC;
        const uint32_t bufA = sb + OFF_STAGE0 + (uint32_t)(c & 1) * STAGE_BYTES;
        #pragma unroll
        for (int h = 0; h < 2; ++h) {
            float4 v[4];
            #pragma unroll
            for (int r = 0; r < 4; ++r) {
                int i4 = (h * 4 + r) * GTHREADS + tid;   // [0,2048)
                int m = i4 >> 4, k4 = i4 & 15;
                int g = s_idx[m];
                v[r] = (g >= 0) ? *(const float4*)(x + (size_t)g * IN_DIM + kb + k4 * 4)
                                : make_float4(0.f, 0.f, 0.f, 0.f);
            }
            #pragma unroll
            for (int r = 0; r < 4; ++r) {
                int i4 = (h * 4 + r) * GTHREADS + tid;
                int m = i4 >> 4, k4 = i4 & 15;
                __half2 h01 = __floats2half2_rn(v[r].x, v[r].y);
                __half2 h23 = __floats2half2_rn(v[r].z, v[r].w);
                *(uint2*)(smem + (bufA - sb) + swz((uint32_t)(m * 128 + k4 * 8))) =
                    make_uint2(h2_as_u32(h01), h2_as_u32(h23));
            }
        }
    };

    // -------- warp/lane constants for ldmatrix --------
    const int mgrp = wid >> 2;      // rows [64*mgrp, +64)
    const int nq   = wid & 3;       // cols [32*nq, +32) within the 128-col tile
    const int j = lane & 7, sub = lane >> 3;

    uint32_t a_base[4], a_xr[4], b_base[2], b_xr[2];
    #pragma unroll
    for (int mt = 0; mt < 4; ++mt) {
        int row = mgrp * 64 + mt * 16 + j + (sub & 1) * 8;
        a_xr[mt]   = (uint32_t)((row & 7) * 16);
        a_base[mt] = (uint32_t)(row * 128) + (uint32_t)((sub >> 1) * 16);
    }
    #pragma unroll
    for (int nt = 0; nt < 2; ++nt) {
        int row = nq * 32 + nt * 16 + (sub >> 1) * 8 + j;
        b_xr[nt]   = (uint32_t)((row & 7) * 16);
        b_base[nt] = (uint32_t)(row * 128) + (uint32_t)((sub & 1) * 16);
    }

    float acc[4][4][4];   // [mt][n8][quad]
    #pragma unroll
    for (int mt = 0; mt < 4; ++mt)
        #pragma unroll
        for (int i = 0; i < 4; ++i)
            #pragma unroll
            for (int q = 0; q < 4; ++q) acc[mt][i][q] = 0.f;

    issueB(0);
    loadA(0);

    for (int c = 0; c < NCHUNK; ++c) {
        const uint32_t stg = sb + OFF_STAGE0 + (uint32_t)(c & 1) * STAGE_BYTES;
        const uint32_t Ah = stg, Bh = stg + 16384u;

        cpa_wait0();              // B(c) arrived
        __syncthreads();          // all warps done with stage (c+1)&1 (chunk c-1)

        if (c + 1 < NCHUNK) issueB(c + 1);    // safe: past the barrier

        // ---- compute chunk c: 4 K16 steps ----
        #pragma unroll
        for (int ks = 0; ks < 4; ++ks) {
            const uint32_t kb = (uint32_t)(ks * 32);
            uint32_t ah[4][4], bhr[2][4];
            #pragma unroll
            for (int mt = 0; mt < 4; ++mt)
                ldsm4(ah[mt], Ah + ((a_base[mt] + kb) ^ a_xr[mt]));
            #pragma unroll
            for (int nt = 0; nt < 2; ++nt)
                ldsm4(bhr[nt], Bh + ((b_base[nt] + kb) ^ b_xr[nt]));
            #pragma unroll
            for (int nt = 0; nt < 2; ++nt)
                #pragma unroll
                for (int mt = 0; mt < 4; ++mt) {
                    mma16816(acc[mt][2 * nt],     ah[mt], bhr[nt][0], bhr[nt][1]);
                    mma16816(acc[mt][2 * nt + 1], ah[mt], bhr[nt][2], bhr[nt][3]);
                }
        }

        if (c + 1 < NCHUNK) loadA(c + 1);     // writes stage (c+1)&1; ordered by
                                              // next iteration's barrier
    }

    // ---- epilogue: bias + scatter-store (streaming, no reuse) ----
    #pragma unroll
    for (int mt = 0; mt < 4; ++mt) {
        const int r0 = mgrp * 64 + mt * 16 + (lane >> 2);
        const int g0 = s_idx[r0];
        const int g1 = s_idx[r0 + 8];
        #pragma unroll
        for (int n8 = 0; n8 < 4; ++n8) {
            const int lcol = nq * 32 + n8 * 8 + (lane & 3) * 2;
            const int col  = nside * BN + lcol;
            const float bv0 = s_bias[lcol], bv1 = s_bias[lcol + 1];
            if (g0 >= 0)
                stcs2(out + (size_t)g0 * OUT_DIM + col,
                      make_float2(acc[mt][n8][0] + bv0, acc[mt][n8][1] + bv1));
            if (g1 >= 0)
                stcs2(out + (size_t)g1 * OUT_DIM + col,
                      make_float2(acc[mt][n8][2] + bv0, acc[mt][n8][3] + bv1));
        }
    }
}

// ============================================================================
// Launch
// ============================================================================
extern "C" void kernel_launch(void* const* d_in, const int* in_sizes, int n_in,
                              void* d_out, int out_size) {
    const float* x     = (const float*)d_in[0];
    const int*   types = (const int*)d_in[1];
    const float* W     = (const float*)d_in[2];
    const float* b     = (const float*)d_in[3];
    float*       out   = (float*)d_out;

    cudaFuncSetAttribute(typed_linear_gemm, cudaFuncAttributeMaxDynamicSharedMemorySize,
                         SMEM_BYTES);

    k_prep1<<<HIST_BLOCKS + 512, 256>>>(W, types);
    k_scan<<<1, 256>>>();
    k_scatter<<<HIST_BLOCKS, 256>>>(types);
    typed_linear_gemm<<<MAXTILES * 2, GTHREADS, SMEM_BYTES>>>(x, b, out);
}

// round 9
// speedup vs baseline: 2.6095x; 1.1761x over previous
#include <cuda_runtime.h>
#include <cuda_fp16.h>
#include <cstdint>

// ============================================================================
// Problem constants
// ============================================================================
#define N_ROWS   65536
#define IN_DIM   256
#define OUT_DIM  256
#define NTYPES   8
#define BM       128                       // rows per block tile
#define BN       128                       // cols per block tile (OUT split in 2)
#define MAXTILES (N_ROWS / BM + NTYPES)    // 520 row-tiles
#define KC       64                        // K-chunk
#define NCHUNK   (IN_DIM / KC)             // 4
#define GTHREADS 256
#define HIST_BLOCKS 64
#define WCONV_BLOCKS 512
#define XCONV_BLOCKS 4096

// SMEM layout (bytes):
//  [0]      s_idx[128]     512B
//  [512]    s_bias[128]    512B
//  [1024]   3 stages x (Ah 16K | Bh 16K) = 96K
#define OFF_STAGE0  1024
#define STAGE_BYTES 32768
#define SMEM_BYTES  99328

// ============================================================================
// Device scratch
// ============================================================================
__device__ int g_counts[NTYPES];   // self-resetting across graph replays
__device__ int g_cursor[NTYPES];   // self-resetting across graph replays
__device__ int g_padstart[NTYPES];
__device__ int g_idx[MAXTILES * BM];
__device__ int g_tiletype[MAXTILES];
__device__ __align__(16) __half g_Wh[NTYPES * OUT_DIM * IN_DIM];
__device__ __align__(16) __half g_xh[N_ROWS * IN_DIM];          // 32 MB fp16 x

// ============================================================================
// Helpers
// ============================================================================
__device__ __forceinline__ uint32_t smem_u32(const void* p) {
    uint32_t a;
    asm("{ .reg .u64 t; cvta.to.shared.u64 t, %1; cvt.u32.u64 %0, t; }" : "=r"(a) : "l"(p));
    return a;
}

__device__ __forceinline__ uint32_t swz(uint32_t off) { return off ^ ((off >> 3) & 0x70); }

__device__ __forceinline__ void cpa16(uint32_t dst, const void* src) {
    asm volatile("cp.async.cg.shared.global [%0], [%1], 16;" :: "r"(dst), "l"(src));
}
__device__ __forceinline__ void cpa_commit() {
    asm volatile("cp.async.commit_group;");
}
template <int N> __device__ __forceinline__ void cpa_wait() {
    asm volatile("cp.async.wait_group %0;" :: "n"(N) : "memory");
}

__device__ __forceinline__ void ldsm4(uint32_t* r, uint32_t addr) {
    asm volatile("ldmatrix.sync.aligned.m8n8.x4.shared.b16 {%0,%1,%2,%3}, [%4];"
                 : "=r"(r[0]), "=r"(r[1]), "=r"(r[2]), "=r"(r[3]) : "r"(addr));
}

__device__ __forceinline__ void mma16816(float* c, const uint32_t* a, uint32_t b0, uint32_t b1) {
    asm volatile("mma.sync.aligned.m16n8k16.row.col.f32.f16.f16.f32 "
                 "{%0,%1,%2,%3}, {%4,%5,%6,%7}, {%8,%9}, {%0,%1,%2,%3};"
                 : "+f"(c[0]), "+f"(c[1]), "+f"(c[2]), "+f"(c[3])
                 : "r"(a[0]), "r"(a[1]), "r"(a[2]), "r"(a[3]), "r"(b0), "r"(b1));
}

__device__ __forceinline__ uint32_t h2_as_u32(__half2 h) {
    return *reinterpret_cast<uint32_t*>(&h);
}

__device__ __forceinline__ void stcs2(float* p, float2 v) {
    asm volatile("st.global.cs.v2.f32 [%0], {%1, %2};" :: "l"(p), "f"(v.x), "f"(v.y));
}

__device__ __forceinline__ uint2 cvt4(float4 v) {
    __half2 h01 = __floats2half2_rn(v.x, v.y);
    __half2 h23 = __floats2half2_rn(v.z, v.w);
    return make_uint2(h2_as_u32(h01), h2_as_u32(h23));
}

// ============================================================================
// k_prep1: [0,64) histogram | [64,576) W->fp16 | [576,4672) x->fp16
// ============================================================================
__global__ void __launch_bounds__(256) k_prep1(const float* __restrict__ W,
                                               const float* __restrict__ x,
                                               const int* __restrict__ types) {
    const int bid = blockIdx.x, tid = threadIdx.x;

    if (bid < HIST_BLOCKS) {
        __shared__ int c[NTYPES];
        if (tid < NTYPES) c[tid] = 0;
        __syncthreads();
        int i = bid * 256 + tid;                       // [0, 16384)
        int4 tv = *(const int4*)(types + i * 4);
        atomicAdd(&c[tv.x], 1);
        atomicAdd(&c[tv.y], 1);
        atomicAdd(&c[tv.z], 1);
        atomicAdd(&c[tv.w], 1);
        __syncthreads();
        if (tid < NTYPES) atomicAdd(&g_counts[tid], c[tid]);
        return;
    }
    if (bid < HIST_BLOCKS + WCONV_BLOCKS) {
        // ---- W convert: fp32 -> fp16 ----
        int i4 = (bid - HIST_BLOCKS) * 256 + tid;      // [0, 131072)
        float4 v = *(const float4*)(W + (size_t)i4 * 4);
        *(uint2*)(g_Wh + (size_t)i4 * 4) = cvt4(v);
        return;
    }
    // ---- x convert: fp32 -> fp16 (4 float4 per thread) ----
    int base = (bid - HIST_BLOCKS - WCONV_BLOCKS) * 1024 + tid;   // float4 idx
    #pragma unroll
    for (int r = 0; r < 4; ++r) {
        int i4 = base + r * 256;                       // [0, 4194304)
        float4 v = *(const float4*)(x + (size_t)i4 * 4);
        *(uint2*)(g_xh + (size_t)i4 * 4) = cvt4(v);
    }
}

// ============================================================================
// k_scan: prefix offsets, tile->type table, padded-slot marking
// ============================================================================
__global__ void k_scan() {
    __shared__ int s_start[NTYPES], s_tiles[NTYPES];
    int tid = threadIdx.x;
    if (tid == 0) {
        int off = 0;
        for (int t = 0; t < NTYPES; t++) {
            s_start[t] = off;
            g_padstart[t] = off;
            int tt = (g_counts[t] + BM - 1) / BM;
            s_tiles[t] = tt;
            off += tt * BM;
        }
    }
    __syncthreads();
    for (int tile = tid; tile < MAXTILES; tile += blockDim.x) {
        int ty = -1;
        int rb = tile * BM;
        for (int t = 0; t < NTYPES; t++)
            if (rb >= s_start[t] && rb < s_start[t] + s_tiles[t] * BM) ty = t;
        g_tiletype[tile] = ty;
    }
    for (int j = tid; j < NTYPES * BM; j += blockDim.x) {
        int t = j / BM, o = j % BM;
        int slot = g_counts[t] + o;
        if (slot < s_tiles[t] * BM) g_idx[s_start[t] + slot] = -1;
    }
}

// ============================================================================
// k_scatter: scatter rows by type + self-reset of counters for graph replay
// ============================================================================
__global__ void __launch_bounds__(256) k_scatter(const int* __restrict__ types) {
    __shared__ int c[NTYPES], base[NTYPES];
    int tid = threadIdx.x;
    if (tid < NTYPES) c[tid] = 0;
    __syncthreads();
    int i = blockIdx.x * 256 + tid;                    // [0, 16384)
    int4 tv = *(const int4*)(types + i * 4);
    int p0 = atomicAdd(&c[tv.x], 1);
    int p1 = atomicAdd(&c[tv.y], 1);
    int p2 = atomicAdd(&c[tv.z], 1);
    int p3 = atomicAdd(&c[tv.w], 1);
    __syncthreads();
    if (tid < NTYPES) base[tid] = atomicAdd(&g_cursor[tid], c[tid]);
    __syncthreads();
    g_idx[g_padstart[tv.x] + base[tv.x] + p0] = i * 4;
    g_idx[g_padstart[tv.y] + base[tv.y] + p1] = i * 4 + 1;
    g_idx[g_padstart[tv.z] + base[tv.z] + p2] = i * 4 + 2;
    g_idx[g_padstart[tv.w] + base[tv.w] + p3] = i * 4 + 3;
    if (tid < NTYPES) {
        atomicSub(&g_counts[tid], c[tid]);
        atomicSub(&g_cursor[tid], c[tid]);
    }
}

// ============================================================================
// Grouped GEMM: block = (row-tile, N-half). D[128,128] = gather(xh)*Wh^T + b
// Pure cp.async + ldmatrix + mma; 3-stage pipeline, prefetch depth 2.
// 8 warps in 2(M)x4(N); warp tile 64x32; 64 fp32 acc/thread; 2 CTAs/SM.
// ============================================================================
__global__ void __launch_bounds__(GTHREADS, 2)
typed_linear_gemm(const float* __restrict__ b, float* __restrict__ out) {
    extern __shared__ char smem[];
    const int tile  = blockIdx.x >> 1;
    const int nside = blockIdx.x & 1;
    const int t = g_tiletype[tile];
    if (t < 0) return;

    const int tid  = threadIdx.x;
    const int wid  = tid >> 5;
    const int lane = tid & 31;
    const uint32_t sb = smem_u32(smem);

    int*   s_idx  = (int*)smem;
    float* s_bias = (float*)(smem + 512);

    if (tid < BM) s_idx[tid] = g_idx[tile * BM + tid];
    if (tid < BN) s_bias[tid] = b[t * OUT_DIM + nside * BN + tid];
    __syncthreads();

    const __half* Wh_t = g_Wh + ((size_t)t * OUT_DIM + nside * BN) * IN_DIM;

    // Per chunk: A = 128 rows x 64 fp16 gathered (1024 x 16B, 4/thread),
    //            B = 128 rows x 64 fp16           (1024 x 16B, 4/thread).
    auto issue_chunk = [&](int c) {
        const int kb = c * KC;
        const uint32_t stg = sb + OFF_STAGE0 + (uint32_t)(c % 3) * STAGE_BYTES;
        #pragma unroll
        for (int r = 0; r < 4; ++r) {
            int i16 = r * GTHREADS + tid;          // [0,1024)
            int m = i16 >> 3, k16 = i16 & 7;
            int g = s_idx[m];
            uint32_t d = swz((uint32_t)(m * 128 + k16 * 16));
            cpa16(stg + d, g_xh + (size_t)(g < 0 ? 0 : g) * IN_DIM + kb + k16 * 8);
        }
        #pragma unroll
        for (int r = 0; r < 4; ++r) {
            int i16 = r * GTHREADS + tid;          // [0,1024)
            int n = i16 >> 3, k16 = i16 & 7;
            uint32_t d = swz((uint32_t)(n * 128 + k16 * 16));
            cpa16(stg + 16384u + d, Wh_t + (size_t)n * IN_DIM + kb + k16 * 8);
        }
        cpa_commit();
    };

    // -------- warp/lane constants for ldmatrix --------
    const int mgrp = wid >> 2;      // rows [64*mgrp, +64)
    const int nq   = wid & 3;       // cols [32*nq, +32) within the 128-col tile
    const int j = lane & 7, sub = lane >> 3;

    uint32_t a_base[4], a_xr[4], b_base[2], b_xr[2];
    #pragma unroll
    for (int mt = 0; mt < 4; ++mt) {
        int row = mgrp * 64 + mt * 16 + j + (sub & 1) * 8;
        a_xr[mt]   = (uint32_t)((row & 7) * 16);
        a_base[mt] = (uint32_t)(row * 128) + (uint32_t)((sub >> 1) * 16);
    }
    #pragma unroll
    for (int nt = 0; nt < 2; ++nt) {
        int row = nq * 32 + nt * 16 + (sub >> 1) * 8 + j;
        b_xr[nt]   = (uint32_t)((row & 7) * 16);
        b_base[nt] = (uint32_t)(row * 128) + (uint32_t)((sub & 1) * 16);
    }

    float acc[4][4][4];   // [mt][n8][quad]
    #pragma unroll
    for (int mt = 0; mt < 4; ++mt)
        #pragma unroll
        for (int i = 0; i < 4; ++i)
            #pragma unroll
            for (int q = 0; q < 4; ++q) acc[mt][i][q] = 0.f;

    issue_chunk(0);
    issue_chunk(1);

    #pragma unroll
    for (int c = 0; c < NCHUNK; ++c) {
        const uint32_t stg = sb + OFF_STAGE0 + (uint32_t)(c % 3) * STAGE_BYTES;
        const uint32_t Ah = stg, Bh = stg + 16384u;

        if (c == NCHUNK - 1) cpa_wait<0>(); else cpa_wait<1>();   // chunk c arrived
        __syncthreads();   // all warps past compute(c-1); stage (c+2)%3 free

        if (c + 2 < NCHUNK) issue_chunk(c + 2);

        // ---- compute chunk c: 4 K16 steps ----
        #pragma unroll
        for (int ks = 0; ks < 4; ++ks) {
            const uint32_t kb = (uint32_t)(ks * 32);
            uint32_t ah[4][4], bhr[2][4];
            #pragma unroll
            for (int mt = 0; mt < 4; ++mt)
                ldsm4(ah[mt], Ah + ((a_base[mt] + kb) ^ a_xr[mt]));
            #pragma unroll
            for (int nt = 0; nt < 2; ++nt)
                ldsm4(bhr[nt], Bh + ((b_base[nt] + kb) ^ b_xr[nt]));
            #pragma unroll
            for (int nt = 0; nt < 2; ++nt)
                #pragma unroll
                for (int mt = 0; mt < 4; ++mt) {
                    mma16816(acc[mt][2 * nt],     ah[mt], bhr[nt][0], bhr[nt][1]);
                    mma16816(acc[mt][2 * nt + 1], ah[mt], bhr[nt][2], bhr[nt][3]);
                }
        }
    }

    // ---- epilogue: bias + scatter-store (streaming) ----
    #pragma unroll
    for (int mt = 0; mt < 4; ++mt) {
        const int r0 = mgrp * 64 + mt * 16 + (lane >> 2);
        const int g0 = s_idx[r0];
        const int g1 = s_idx[r0 + 8];
        #pragma unroll
        for (int n8 = 0; n8 < 4; ++n8) {
            const int lcol = nq * 32 + n8 * 8 + (lane & 3) * 2;
            const int col  = nside * BN + lcol;
            const float bv0 = s_bias[lcol], bv1 = s_bias[lcol + 1];
            if (g0 >= 0)
                stcs2(out + (size_t)g0 * OUT_DIM + col,
                      make_float2(acc[mt][n8][0] + bv0, acc[mt][n8][1] + bv1));
            if (g1 >= 0)
                stcs2(out + (size_t)g1 * OUT_DIM + col,
                      make_float2(acc[mt][n8][2] + bv0, acc[mt][n8][3] + bv1));
        }
    }
}

// ============================================================================
// Launch
// ============================================================================
extern "C" void kernel_launch(void* const* d_in, const int* in_sizes, int n_in,
                              void* d_out, int out_size) {
    const float* x     = (const float*)d_in[0];
    const int*   types = (const int*)d_in[1];
    const float* W     = (const float*)d_in[2];
    const float* b     = (const float*)d_in[3];
    float*       out   = (float*)d_out;

    cudaFuncSetAttribute(typed_linear_gemm, cudaFuncAttributeMaxDynamicSharedMemorySize,
                         SMEM_BYTES);

    k_prep1<<<HIST_BLOCKS + WCONV_BLOCKS + XCONV_BLOCKS, 256>>>(W, x, types);
    k_scan<<<1, 256>>>();
    k_scatter<<<HIST_BLOCKS, 256>>>(types);
    typed_linear_gemm<<<MAXTILES * 2, GTHREADS, SMEM_BYTES>>>(b, out);
}